// round 1
// baseline (speedup 1.0000x reference)
#include <cuda_runtime.h>
#include <cuda_bf16.h>
#include <math.h>

// Model constants
#define BB   2
#define TT   2048
#define LL   6
#define HH   12
#define DD   768
#define HDIM 64
#define VV   32000
#define MM   (BB*TT)          // 4096 tokens

// Scratch (device globals; no allocation allowed)
__device__ float g_x  [MM * DD];          // residual stream
__device__ float g_h  [MM * DD];          // LN output
__device__ float g_qkv[MM * 3 * DD];      // qkv projection
__device__ float g_y  [MM * DD];          // attention output
__device__ float g_ff [MM * 4 * DD];      // ff hidden

// ---------------------------------------------------------------------------
// Embedding: x[tok] = tok_emb[idx[tok]] + pos_emb[tok % T]
// ---------------------------------------------------------------------------
__global__ __launch_bounds__(256) void embed_kernel(
    const int* __restrict__ idx, const float* __restrict__ tok_emb,
    const float* __restrict__ pos_emb, float* __restrict__ x)
{
    int tok = blockIdx.x;
    int id  = idx[tok];
    int p   = tok % TT;
    const float* te = tok_emb + (size_t)id * DD;
    const float* pe = pos_emb + (size_t)p  * DD;
    float* xr = x + (size_t)tok * DD;
    for (int d = threadIdx.x; d < DD; d += 256)
        xr[d] = te[d] + pe[d];
}

// ---------------------------------------------------------------------------
// LayerNorm: one block per token, D = 768 = 3 * 256
// ---------------------------------------------------------------------------
__global__ __launch_bounds__(256) void ln_kernel(
    const float* __restrict__ x, const float* __restrict__ w,
    const float* __restrict__ b, float* __restrict__ o)
{
    int tok = blockIdx.x;
    int t   = threadIdx.x;
    const float* xr = x + (size_t)tok * DD;
    float v0 = xr[t], v1 = xr[t + 256], v2 = xr[t + 512];
    float s  = v0 + v1 + v2;
    float s2 = v0*v0 + v1*v1 + v2*v2;
    #pragma unroll
    for (int off = 16; off; off >>= 1) {
        s  += __shfl_down_sync(0xffffffffu, s,  off);
        s2 += __shfl_down_sync(0xffffffffu, s2, off);
    }
    __shared__ float red[16];
    __shared__ float mean_s, rstd_s;
    int wid = t >> 5, lid = t & 31;
    if (lid == 0) { red[wid] = s; red[8 + wid] = s2; }
    __syncthreads();
    if (t == 0) {
        float S = 0.f, S2 = 0.f;
        #pragma unroll
        for (int i = 0; i < 8; i++) { S += red[i]; S2 += red[8 + i]; }
        float mean = S * (1.0f / DD);
        float var  = S2 * (1.0f / DD) - mean * mean;
        mean_s = mean;
        rstd_s = rsqrtf(var + 1e-5f);
    }
    __syncthreads();
    float mean = mean_s, rstd = rstd_s;
    float* orow = o + (size_t)tok * DD;
    orow[t      ] = (v0 - mean) * rstd * w[t      ] + b[t      ];
    orow[t + 256] = (v1 - mean) * rstd * w[t + 256] + b[t + 256];
    orow[t + 512] = (v2 - mean) * rstd * w[t + 512] + b[t + 512];
}

// ---------------------------------------------------------------------------
// GEMM: C[M,N] = A[M,K] @ B  (+ epilogue).  128x128x8 tile, 8x8 per thread.
//   TRANSB=0: B is [K,N] row-major.  TRANSB=1: B is [N,K] row-major (B^T).
//   EPI=0: store.  EPI=1: C = R + A@B.  EPI=2: C = gelu(A@B) (exact).
// Requires: M%128==0, N%128==0, K%8==0 (true for every call here).
// ---------------------------------------------------------------------------
__device__ __forceinline__ float gelu_exact(float v) {
    return 0.5f * v * (1.0f + erff(v * 0.70710678118654752f));
}

template<int EPI, int TRANSB>
__global__ __launch_bounds__(256) void gemm128(
    const float* __restrict__ A, const float* __restrict__ B,
    const float* __restrict__ R, float* __restrict__ C,
    int M, int N, int K)
{
    __shared__ float As[8][128];
    __shared__ float Bs[8][128];
    const int t  = threadIdx.x;
    const int bm = blockIdx.y * 128;
    const int bn = blockIdx.x * 128;
    const int am  = t >> 1;            // 0..127 (A row / B^T row within tile)
    const int ak  = (t & 1) * 4;       // k quad
    const int bk  = t >> 5;            // 0..7   (B row for non-trans)
    const int bn4 = (t & 31) * 4;      // col quad
    const int tx4 = (t & 15) * 4;      // thread col base (split 4+4)
    const int ty4 = (t >> 4) * 4;      // thread row base (split 4+4)

    float acc[8][8];
    #pragma unroll
    for (int i = 0; i < 8; i++)
        #pragma unroll
        for (int j = 0; j < 8; j++) acc[i][j] = 0.f;

    const float* Ap = A + (size_t)(bm + am) * K + ak;
    const float* Bp = TRANSB ? (B + (size_t)(bn + am) * K + ak)
                             : (B + (size_t)bk * N + bn + bn4);

    for (int k0 = 0; k0 < K; k0 += 8) {
        float4 av = *(const float4*)(Ap + k0);
        As[ak + 0][am] = av.x; As[ak + 1][am] = av.y;
        As[ak + 2][am] = av.z; As[ak + 3][am] = av.w;
        if (TRANSB) {
            float4 bv = *(const float4*)(Bp + k0);
            Bs[ak + 0][am] = bv.x; Bs[ak + 1][am] = bv.y;
            Bs[ak + 2][am] = bv.z; Bs[ak + 3][am] = bv.w;
        } else {
            float4 bv = *(const float4*)(Bp + (size_t)k0 * N);
            *(float4*)&Bs[bk][bn4] = bv;
        }
        __syncthreads();
        #pragma unroll
        for (int kk = 0; kk < 8; kk++) {
            float4 a0 = *(const float4*)&As[kk][ty4];
            float4 a1 = *(const float4*)&As[kk][ty4 + 64];
            float4 b0 = *(const float4*)&Bs[kk][tx4];
            float4 b1 = *(const float4*)&Bs[kk][tx4 + 64];
            float a[8] = {a0.x,a0.y,a0.z,a0.w,a1.x,a1.y,a1.z,a1.w};
            float bb[8] = {b0.x,b0.y,b0.z,b0.w,b1.x,b1.y,b1.z,b1.w};
            #pragma unroll
            for (int i = 0; i < 8; i++)
                #pragma unroll
                for (int j = 0; j < 8; j++)
                    acc[i][j] = fmaf(a[i], bb[j], acc[i][j]);
        }
        __syncthreads();
    }

    #pragma unroll
    for (int i = 0; i < 8; i++) {
        int m = bm + ((i < 4) ? (ty4 + i) : (64 + ty4 + i - 4));
        #pragma unroll
        for (int half = 0; half < 2; half++) {
            size_t off = (size_t)m * N + bn + tx4 + half * 64;
            float4 v;
            v.x = acc[i][half * 4 + 0];
            v.y = acc[i][half * 4 + 1];
            v.z = acc[i][half * 4 + 2];
            v.w = acc[i][half * 4 + 3];
            if (EPI == 1) {
                float4 r = *(const float4*)(R + off);
                v.x += r.x; v.y += r.y; v.z += r.z; v.w += r.w;
            }
            if (EPI == 2) {
                v.x = gelu_exact(v.x); v.y = gelu_exact(v.y);
                v.z = gelu_exact(v.z); v.w = gelu_exact(v.w);
            }
            *(float4*)(C + off) = v;
        }
    }
}

// ---------------------------------------------------------------------------
// Flash attention (causal, HD=64). grid = (T/64, H, B), 256 threads.
// qkv layout: [token][3*D], q at h*64, k at 768+h*64, v at 1536+h*64.
// Online softmax with 64x64 tiles. Dynamic SMEM ~70.4 KB.
// ---------------------------------------------------------------------------
#define FPAD 68
__global__ __launch_bounds__(256) void flash_kernel(
    const float* __restrict__ qkv, float* __restrict__ y)
{
    extern __shared__ float sm[];
    float* Qt = sm;                   // [64 k][68]  (k-major, transposed)
    float* Kt = Qt + 64 * FPAD;       // [64 k][68]
    float* Vs = Kt + 64 * FPAD;       // [64 j][68]  (row-major)
    float* Ps = Vs + 64 * FPAD;       // [64 r][68]
    float* mS = Ps + 64 * FPAD;       // [64]
    float* lS = mS + 64;              // [64]
    float* aS = lS + 64;              // [64]

    const int qt = blockIdx.x, h = blockIdx.y, b = blockIdx.z;
    const int t  = threadIdx.x;
    const int lr = t >> 4;            // 0..15 (load row group)
    const int qc = (t & 15) * 4;      // load col quad
    const int tx = (t & 15) * 4;      // compute col base
    const int ty = (t >> 4) * 4;      // compute row base

    // load Q tile (transposed into Qt)
    #pragma unroll
    for (int i = 0; i < 4; i++) {
        int rr  = lr + i * 16;
        int tok = b * TT + qt * 64 + rr;
        float4 v = *(const float4*)(qkv + (size_t)tok * (3 * DD) + h * HDIM + qc);
        Qt[(qc + 0) * FPAD + rr] = v.x;
        Qt[(qc + 1) * FPAD + rr] = v.y;
        Qt[(qc + 2) * FPAD + rr] = v.z;
        Qt[(qc + 3) * FPAD + rr] = v.w;
    }
    if (t < 64) { mS[t] = -1e30f; lS[t] = 0.f; }

    float acc[4][4];
    #pragma unroll
    for (int i = 0; i < 4; i++)
        #pragma unroll
        for (int j = 0; j < 4; j++) acc[i][j] = 0.f;

    for (int kt = 0; kt <= qt; kt++) {
        // load K (transposed) and V (row-major) tiles
        #pragma unroll
        for (int i = 0; i < 4; i++) {
            int rr  = lr + i * 16;
            int tok = b * TT + kt * 64 + rr;
            const float* base = qkv + (size_t)tok * (3 * DD) + h * HDIM + qc;
            float4 kv = *(const float4*)(base + DD);
            Kt[(qc + 0) * FPAD + rr] = kv.x;
            Kt[(qc + 1) * FPAD + rr] = kv.y;
            Kt[(qc + 2) * FPAD + rr] = kv.z;
            Kt[(qc + 3) * FPAD + rr] = kv.w;
            float4 vv = *(const float4*)(base + 2 * DD);
            *(float4*)&Vs[rr * FPAD + qc] = vv;
        }
        __syncthreads();

        // S = Q K^T * 0.125, causal mask, into Ps
        float s[4][4];
        #pragma unroll
        for (int i = 0; i < 4; i++)
            #pragma unroll
            for (int j = 0; j < 4; j++) s[i][j] = 0.f;
        #pragma unroll 8
        for (int kk = 0; kk < 64; kk++) {
            float4 qv = *(const float4*)&Qt[kk * FPAD + ty];
            float4 kv = *(const float4*)&Kt[kk * FPAD + tx];
            float qa[4] = {qv.x, qv.y, qv.z, qv.w};
            float ka[4] = {kv.x, kv.y, kv.z, kv.w};
            #pragma unroll
            for (int i = 0; i < 4; i++)
                #pragma unroll
                for (int j = 0; j < 4; j++)
                    s[i][j] = fmaf(qa[i], ka[j], s[i][j]);
        }
        #pragma unroll
        for (int i = 0; i < 4; i++) {
            int gr = qt * 64 + ty + i;
            float4 v;
            float vals[4];
            #pragma unroll
            for (int j = 0; j < 4; j++) {
                int gc = kt * 64 + tx + j;
                vals[j] = (gc > gr) ? -1e30f : s[i][j] * 0.125f;
            }
            v.x = vals[0]; v.y = vals[1]; v.z = vals[2]; v.w = vals[3];
            *(float4*)&Ps[(ty + i) * FPAD + tx] = v;
        }
        __syncthreads();

        // row pass: online softmax bookkeeping (one thread per row)
        if (t < 64) {
            float mold = mS[t];
            float mx = -1e30f;
            #pragma unroll 8
            for (int j = 0; j < 64; j++) mx = fmaxf(mx, Ps[t * FPAD + j]);
            float mn = fmaxf(mold, mx);
            float a  = expf(mold - mn);
            float sum = 0.f;
            #pragma unroll 8
            for (int j = 0; j < 64; j++) {
                float p = expf(Ps[t * FPAD + j] - mn);
                Ps[t * FPAD + j] = p;
                sum += p;
            }
            lS[t] = lS[t] * a + sum;
            mS[t] = mn;
            aS[t] = a;
        }
        __syncthreads();

        // O = O*alpha + P @ V
        float av[4];
        #pragma unroll
        for (int i = 0; i < 4; i++) av[i] = aS[ty + i];
        #pragma unroll
        for (int i = 0; i < 4; i++)
            #pragma unroll
            for (int j = 0; j < 4; j++) acc[i][j] *= av[i];
        #pragma unroll 8
        for (int kk = 0; kk < 64; kk++) {
            float pv[4];
            #pragma unroll
            for (int i = 0; i < 4; i++) pv[i] = Ps[(ty + i) * FPAD + kk];
            float4 vv = *(const float4*)&Vs[kk * FPAD + tx];
            float va[4] = {vv.x, vv.y, vv.z, vv.w};
            #pragma unroll
            for (int i = 0; i < 4; i++)
                #pragma unroll
                for (int j = 0; j < 4; j++)
                    acc[i][j] = fmaf(pv[i], va[j], acc[i][j]);
        }
        __syncthreads();   // before next tile overwrites Kt/Vs/Ps
    }

    // write y[token][h*64 + c] = acc / l
    #pragma unroll
    for (int i = 0; i < 4; i++) {
        int tok   = b * TT + qt * 64 + ty + i;
        float inv = 1.0f / lS[ty + i];
        float4 o;
        o.x = acc[i][0] * inv; o.y = acc[i][1] * inv;
        o.z = acc[i][2] * inv; o.w = acc[i][3] * inv;
        *(float4*)(y + (size_t)tok * DD + h * HDIM + tx) = o;
    }
}

// ---------------------------------------------------------------------------
extern "C" void kernel_launch(void* const* d_in, const int* in_sizes, int n_in,
                              void* d_out, int out_size)
{
    const int*   idx     = (const int*)  d_in[0];
    const float* tok_emb = (const float*)d_in[1];
    const float* pos_emb = (const float*)d_in[2];
    const float* ln1_w   = (const float*)d_in[3];
    const float* ln1_b   = (const float*)d_in[4];
    const float* qkv_w   = (const float*)d_in[5];
    const float* out_w   = (const float*)d_in[6];
    const float* ln2_w   = (const float*)d_in[7];
    const float* ln2_b   = (const float*)d_in[8];
    const float* ff1_w   = (const float*)d_in[9];
    const float* ff2_w   = (const float*)d_in[10];
    const float* lnf_w   = (const float*)d_in[11];
    const float* lnf_b   = (const float*)d_in[12];
    float* out = (float*)d_out;

    float *x, *h, *qkv, *y, *ff;
    cudaGetSymbolAddress((void**)&x,   g_x);
    cudaGetSymbolAddress((void**)&h,   g_h);
    cudaGetSymbolAddress((void**)&qkv, g_qkv);
    cudaGetSymbolAddress((void**)&y,   g_y);
    cudaGetSymbolAddress((void**)&ff,  g_ff);

    const int FLASH_SMEM = (4 * 64 * FPAD + 3 * 64) * sizeof(float);  // 70400 B
    cudaFuncSetAttribute(flash_kernel,
                         cudaFuncAttributeMaxDynamicSharedMemorySize, FLASH_SMEM);

    embed_kernel<<<MM, 256>>>(idx, tok_emb, pos_emb, x);

    for (int l = 0; l < LL; l++) {
        ln_kernel<<<MM, 256>>>(x, ln1_w + l * DD, ln1_b + l * DD, h);
        gemm128<0, 0><<<dim3(3 * DD / 128, MM / 128), 256>>>(
            h, qkv_w + (size_t)l * DD * 3 * DD, nullptr, qkv, MM, 3 * DD, DD);
        flash_kernel<<<dim3(TT / 64, HH, BB), 256, FLASH_SMEM>>>(qkv, y);
        gemm128<1, 0><<<dim3(DD / 128, MM / 128), 256>>>(
            y, out_w + (size_t)l * DD * DD, x, x, MM, DD, DD);
        ln_kernel<<<MM, 256>>>(x, ln2_w + l * DD, ln2_b + l * DD, h);
        gemm128<2, 0><<<dim3(4 * DD / 128, MM / 128), 256>>>(
            h, ff1_w + (size_t)l * DD * 4 * DD, nullptr, ff, MM, 4 * DD, DD);
        gemm128<1, 0><<<dim3(DD / 128, MM / 128), 256>>>(
            ff, ff2_w + (size_t)l * 4 * DD * DD, x, x, MM, DD, 4 * DD);
    }

    ln_kernel<<<MM, 256>>>(x, lnf_w, lnf_b, h);
    gemm128<0, 1><<<dim3(VV / 128, MM / 128), 256>>>(
        h, tok_emb, nullptr, out, MM, VV, DD);
}

// round 3
// speedup vs baseline: 1.6795x; 1.6795x over previous
#include <cuda_runtime.h>
#include <cuda_bf16.h>
#include <math.h>
#include <stdint.h>

#define BB 2
#define TT 2048
#define LL 6
#define HH 12
#define DD 768
#define HDIM 64
#define VV 32000
#define MM (BB*TT)          // 4096 tokens

// ---------------------------------------------------------------------------
// Scratch (device globals; no allocation allowed)
// ---------------------------------------------------------------------------
__device__ float g_x  [MM * DD];            // residual stream (fp32)
__device__ float g_qkv[MM * 3 * DD];        // qkv projection (fp32, flash input)
__device__ __nv_bfloat16 g_h_hi[MM * DD],      g_h_lo[MM * DD];       // LN out split
__device__ __nv_bfloat16 g_y_hi[MM * DD],      g_y_lo[MM * DD];       // attn out split
__device__ __nv_bfloat16 g_ff_hi[MM * 4 * DD], g_ff_lo[MM * 4 * DD];  // gelu out split
// transposed + split weights [N,K]
__device__ __nv_bfloat16 g_qkvT_hi[LL * 3 * DD * DD], g_qkvT_lo[LL * 3 * DD * DD];
__device__ __nv_bfloat16 g_outT_hi[LL * DD * DD],     g_outT_lo[LL * DD * DD];
__device__ __nv_bfloat16 g_ff1T_hi[LL * 4 * DD * DD], g_ff1T_lo[LL * 4 * DD * DD];
__device__ __nv_bfloat16 g_ff2T_hi[LL * 4 * DD * DD], g_ff2T_lo[LL * 4 * DD * DD];
__device__ __nv_bfloat16 g_emb_hi[VV * DD],           g_emb_lo[VV * DD];

// ---------------------------------------------------------------------------
// PTX helpers (plain sm_103-safe: mma.sync + ldmatrix + cp.async only)
// ---------------------------------------------------------------------------
__device__ __forceinline__ uint32_t smem_u32(const void* p) {
    uint32_t a;
    asm("{ .reg .u64 t; cvta.to.shared.u64 t, %1; cvt.u32.u64 %0, t; }"
        : "=r"(a) : "l"(p));
    return a;
}

__device__ __forceinline__ void cpa16(uint32_t dst, const void* src) {
    asm volatile("cp.async.cg.shared.global [%0], [%1], 16;" :: "r"(dst), "l"(src));
}
#define CPA_COMMIT() asm volatile("cp.async.commit_group;" ::: "memory")

__device__ __forceinline__ void ldsm4(uint32_t* r, uint32_t addr) {
    asm volatile("ldmatrix.sync.aligned.m8n8.x4.shared.b16 {%0,%1,%2,%3}, [%4];"
        : "=r"(r[0]), "=r"(r[1]), "=r"(r[2]), "=r"(r[3]) : "r"(addr));
}

__device__ __forceinline__ void mma_bf16(float* d, const uint32_t* a, const uint32_t* b) {
    asm volatile(
        "mma.sync.aligned.m16n8k16.row.col.f32.bf16.bf16.f32 "
        "{%0,%1,%2,%3}, {%4,%5,%6,%7}, {%8,%9}, {%0,%1,%2,%3};"
        : "+f"(d[0]), "+f"(d[1]), "+f"(d[2]), "+f"(d[3])
        : "r"(a[0]), "r"(a[1]), "r"(a[2]), "r"(a[3]), "r"(b[0]), "r"(b[1]));
}

__device__ __forceinline__ void split_bf(float v, __nv_bfloat16& hi, __nv_bfloat16& lo) {
    hi = __float2bfloat16(v);
    lo = __float2bfloat16(v - __bfloat162float(hi));
}
__device__ __forceinline__ float gelu_exact(float v) {
    return 0.5f * v * (1.0f + erff(v * 0.70710678118654752f));
}

// ---------------------------------------------------------------------------
// Weight prep: transpose+split W[K,N] -> Thi/Tlo [N,K]
// ---------------------------------------------------------------------------
__global__ __launch_bounds__(256) void wprep_T(
    const float* __restrict__ W, __nv_bfloat16* __restrict__ Thi,
    __nv_bfloat16* __restrict__ Tlo, int K, int N)
{
    __shared__ float tile[32][33];
    int n0 = blockIdx.x * 32, k0 = blockIdx.y * 32;
    int tx = threadIdx.x & 31, ty = threadIdx.x >> 5;
    #pragma unroll
    for (int i = ty; i < 32; i += 8)
        tile[i][tx] = W[(size_t)(k0 + i) * N + n0 + tx];
    __syncthreads();
    #pragma unroll
    for (int i = ty; i < 32; i += 8) {
        float v = tile[tx][i];
        size_t o = (size_t)(n0 + i) * K + k0 + tx;
        __nv_bfloat16 h, l; split_bf(v, h, l);
        Thi[o] = h; Tlo[o] = l;
    }
}

// split without transpose (tok_emb): n4 float4 elements
__global__ __launch_bounds__(256) void wprep_S(
    const float4* __restrict__ W, __nv_bfloat16* __restrict__ hi,
    __nv_bfloat16* __restrict__ lo, int n4)
{
    for (int i = blockIdx.x * blockDim.x + threadIdx.x; i < n4;
         i += gridDim.x * blockDim.x) {
        float4 v = W[i];
        __nv_bfloat16 h0, h1, h2, h3, l0, l1, l2, l3;
        split_bf(v.x, h0, l0); split_bf(v.y, h1, l1);
        split_bf(v.z, h2, l2); split_bf(v.w, h3, l3);
        ((__nv_bfloat162*)hi)[i * 2    ] = __halves2bfloat162(h0, h1);
        ((__nv_bfloat162*)hi)[i * 2 + 1] = __halves2bfloat162(h2, h3);
        ((__nv_bfloat162*)lo)[i * 2    ] = __halves2bfloat162(l0, l1);
        ((__nv_bfloat162*)lo)[i * 2 + 1] = __halves2bfloat162(l2, l3);
    }
}

// ---------------------------------------------------------------------------
// Embedding
// ---------------------------------------------------------------------------
__global__ __launch_bounds__(256) void embed_kernel(
    const int* __restrict__ idx, const float* __restrict__ tok_emb,
    const float* __restrict__ pos_emb, float* __restrict__ x)
{
    int tok = blockIdx.x;
    int id  = idx[tok];
    int p   = tok % TT;
    const float* te = tok_emb + (size_t)id * DD;
    const float* pe = pos_emb + (size_t)p  * DD;
    float* xr = x + (size_t)tok * DD;
    for (int d = threadIdx.x; d < DD; d += 256)
        xr[d] = te[d] + pe[d];
}

// ---------------------------------------------------------------------------
// LayerNorm -> split bf16 hi/lo outputs
// ---------------------------------------------------------------------------
__global__ __launch_bounds__(256) void ln_kernel(
    const float* __restrict__ x, const float* __restrict__ w,
    const float* __restrict__ b, __nv_bfloat16* __restrict__ ohi,
    __nv_bfloat16* __restrict__ olo)
{
    int tok = blockIdx.x;
    int t   = threadIdx.x;
    const float* xr = x + (size_t)tok * DD;
    float v0 = xr[t], v1 = xr[t + 256], v2 = xr[t + 512];
    float s  = v0 + v1 + v2;
    float s2 = v0*v0 + v1*v1 + v2*v2;
    #pragma unroll
    for (int off = 16; off; off >>= 1) {
        s  += __shfl_down_sync(0xffffffffu, s,  off);
        s2 += __shfl_down_sync(0xffffffffu, s2, off);
    }
    __shared__ float red[16];
    __shared__ float mean_s, rstd_s;
    int wid = t >> 5, lid = t & 31;
    if (lid == 0) { red[wid] = s; red[8 + wid] = s2; }
    __syncthreads();
    if (t == 0) {
        float S = 0.f, S2 = 0.f;
        #pragma unroll
        for (int i = 0; i < 8; i++) { S += red[i]; S2 += red[8 + i]; }
        float mean = S * (1.0f / DD);
        float var  = S2 * (1.0f / DD) - mean * mean;
        mean_s = mean;
        rstd_s = rsqrtf(var + 1e-5f);
    }
    __syncthreads();
    float mean = mean_s, rstd = rstd_s;
    size_t base = (size_t)tok * DD;
    #pragma unroll
    for (int q = 0; q < 3; q++) {
        int d = t + q * 256;
        float v = (q == 0 ? v0 : (q == 1 ? v1 : v2));
        float o = (v - mean) * rstd * w[d] + b[d];
        __nv_bfloat16 h, l; split_bf(o, h, l);
        ohi[base + d] = h; olo[base + d] = l;
    }
}

// ---------------------------------------------------------------------------
// Flash attention (fp32, causal, HD=64) -> split bf16 output
// ---------------------------------------------------------------------------
#define FPAD 68
__global__ __launch_bounds__(256) void flash_kernel(
    const float* __restrict__ qkv, __nv_bfloat16* __restrict__ y_hi,
    __nv_bfloat16* __restrict__ y_lo)
{
    extern __shared__ float sm[];
    float* Qt = sm;
    float* Kt = Qt + 64 * FPAD;
    float* Vs = Kt + 64 * FPAD;
    float* Ps = Vs + 64 * FPAD;
    float* mS = Ps + 64 * FPAD;
    float* lS = mS + 64;
    float* aS = lS + 64;

    const int qt = blockIdx.x, h = blockIdx.y, b = blockIdx.z;
    const int t  = threadIdx.x;
    const int lr = t >> 4;
    const int qc = (t & 15) * 4;
    const int tx = (t & 15) * 4;
    const int ty = (t >> 4) * 4;

    #pragma unroll
    for (int i = 0; i < 4; i++) {
        int rr  = lr + i * 16;
        int tok = b * TT + qt * 64 + rr;
        float4 v = *(const float4*)(qkv + (size_t)tok * (3 * DD) + h * HDIM + qc);
        Qt[(qc + 0) * FPAD + rr] = v.x;
        Qt[(qc + 1) * FPAD + rr] = v.y;
        Qt[(qc + 2) * FPAD + rr] = v.z;
        Qt[(qc + 3) * FPAD + rr] = v.w;
    }
    if (t < 64) { mS[t] = -1e30f; lS[t] = 0.f; }

    float acc[4][4];
    #pragma unroll
    for (int i = 0; i < 4; i++)
        #pragma unroll
        for (int j = 0; j < 4; j++) acc[i][j] = 0.f;

    for (int kt = 0; kt <= qt; kt++) {
        #pragma unroll
        for (int i = 0; i < 4; i++) {
            int rr  = lr + i * 16;
            int tok = b * TT + kt * 64 + rr;
            const float* base = qkv + (size_t)tok * (3 * DD) + h * HDIM + qc;
            float4 kv = *(const float4*)(base + DD);
            Kt[(qc + 0) * FPAD + rr] = kv.x;
            Kt[(qc + 1) * FPAD + rr] = kv.y;
            Kt[(qc + 2) * FPAD + rr] = kv.z;
            Kt[(qc + 3) * FPAD + rr] = kv.w;
            float4 vv = *(const float4*)(base + 2 * DD);
            *(float4*)&Vs[rr * FPAD + qc] = vv;
        }
        __syncthreads();

        float s[4][4];
        #pragma unroll
        for (int i = 0; i < 4; i++)
            #pragma unroll
            for (int j = 0; j < 4; j++) s[i][j] = 0.f;
        #pragma unroll 8
        for (int kk = 0; kk < 64; kk++) {
            float4 qv = *(const float4*)&Qt[kk * FPAD + ty];
            float4 kv = *(const float4*)&Kt[kk * FPAD + tx];
            float qa[4] = {qv.x, qv.y, qv.z, qv.w};
            float ka[4] = {kv.x, kv.y, kv.z, kv.w};
            #pragma unroll
            for (int i = 0; i < 4; i++)
                #pragma unroll
                for (int j = 0; j < 4; j++)
                    s[i][j] = fmaf(qa[i], ka[j], s[i][j]);
        }
        #pragma unroll
        for (int i = 0; i < 4; i++) {
            int gr = qt * 64 + ty + i;
            float vals[4];
            #pragma unroll
            for (int j = 0; j < 4; j++) {
                int gc = kt * 64 + tx + j;
                vals[j] = (gc > gr) ? -1e30f : s[i][j] * 0.125f;
            }
            float4 v; v.x = vals[0]; v.y = vals[1]; v.z = vals[2]; v.w = vals[3];
            *(float4*)&Ps[(ty + i) * FPAD + tx] = v;
        }
        __syncthreads();

        if (t < 64) {
            float mold = mS[t];
            float mx = -1e30f;
            #pragma unroll 8
            for (int j = 0; j < 64; j++) mx = fmaxf(mx, Ps[t * FPAD + j]);
            float mn = fmaxf(mold, mx);
            float a  = expf(mold - mn);
            float sum = 0.f;
            #pragma unroll 8
            for (int j = 0; j < 64; j++) {
                float p = expf(Ps[t * FPAD + j] - mn);
                Ps[t * FPAD + j] = p;
                sum += p;
            }
            lS[t] = lS[t] * a + sum;
            mS[t] = mn;
            aS[t] = a;
        }
        __syncthreads();

        float av[4];
        #pragma unroll
        for (int i = 0; i < 4; i++) av[i] = aS[ty + i];
        #pragma unroll
        for (int i = 0; i < 4; i++)
            #pragma unroll
            for (int j = 0; j < 4; j++) acc[i][j] *= av[i];
        #pragma unroll 8
        for (int kk = 0; kk < 64; kk++) {
            float pv[4];
            #pragma unroll
            for (int i = 0; i < 4; i++) pv[i] = Ps[(ty + i) * FPAD + kk];
            float4 vv = *(const float4*)&Vs[kk * FPAD + tx];
            float va[4] = {vv.x, vv.y, vv.z, vv.w};
            #pragma unroll
            for (int i = 0; i < 4; i++)
                #pragma unroll
                for (int j = 0; j < 4; j++)
                    acc[i][j] = fmaf(pv[i], va[j], acc[i][j]);
        }
        __syncthreads();
    }

    #pragma unroll
    for (int i = 0; i < 4; i++) {
        int tok   = b * TT + qt * 64 + ty + i;
        float inv = 1.0f / lS[ty + i];
        size_t base = (size_t)tok * DD + h * HDIM + tx;
        __nv_bfloat16 h0, h1, h2, h3, l0, l1, l2, l3;
        split_bf(acc[i][0] * inv, h0, l0);
        split_bf(acc[i][1] * inv, h1, l1);
        split_bf(acc[i][2] * inv, h2, l2);
        split_bf(acc[i][3] * inv, h3, l3);
        *(__nv_bfloat162*)(y_hi + base    ) = __halves2bfloat162(h0, h1);
        *(__nv_bfloat162*)(y_hi + base + 2) = __halves2bfloat162(h2, h3);
        *(__nv_bfloat162*)(y_lo + base    ) = __halves2bfloat162(l0, l1);
        *(__nv_bfloat162*)(y_lo + base + 2) = __halves2bfloat162(l2, l3);
    }
}

// ---------------------------------------------------------------------------
// HMMA GEMM (mma.sync bf16, 3-term split): C[M,N] = A @ B^T
// A* [M,K] bf16 row-major, B* [N,K] bf16 row-major.
// CTA tile 128x128, K-step 64, double-buffered cp.async.
// 8 warps: 4 (M) x 2 (N); warp tile 32x64; mma m16n8k16.
// EPI: 0 = store fp32 Cf; 1 = Cf = R + acc; 2 = gelu -> split Chi/Clo.
// Requires M%128==0, N%128==0, K%64==0.
// ---------------------------------------------------------------------------
#define GPITCH 144                 // bytes per smem row (64 bf16 = 128B + 16 pad)
#define GMAT   18432               // 128 rows * 144B
#define GSTAGE (4 * GMAT)          // Ahi, Alo, Bhi, Blo
#define GEMM_SMEM (2 * GSTAGE)     // 147456 B

template<int EPI>
__global__ __launch_bounds__(256, 1) void gemm_mma(
    const __nv_bfloat16* __restrict__ Ahi, const __nv_bfloat16* __restrict__ Alo,
    const __nv_bfloat16* __restrict__ Bhi, const __nv_bfloat16* __restrict__ Blo,
    const float* __restrict__ R, float* __restrict__ Cf,
    __nv_bfloat16* __restrict__ Chi, __nv_bfloat16* __restrict__ Clo,
    int M, int N, int K)
{
    extern __shared__ char smem[];
    const uint32_t sb = smem_u32(smem);
    const int t    = threadIdx.x;
    const int bm   = blockIdx.y * 128;
    const int bn   = blockIdx.x * 128;
    const int NK   = K >> 6;
    const int lane = t & 31;
    const int w    = t >> 5;
    const int wm   = w & 3;          // 4 m-groups of 32 rows
    const int wn   = w >> 2;         // 2 n-groups of 64 cols

    // ---- stage loader: each thread does 16 cp.async of 16B ----
    const int lrow  = t >> 1;        // 0..127
    const int lhalf = t & 1;         // which 32-element half of the 64-wide row
    auto load_stage = [&](int s, int kt) {
        const int koff = kt * 64 + lhalf * 32;
        const uint32_t dst0 = sb + s * GSTAGE + lrow * GPITCH + lhalf * 64;
        const __nv_bfloat16* src[4];
        src[0] = Ahi + (size_t)(bm + lrow) * K + koff;
        src[1] = Alo + (size_t)(bm + lrow) * K + koff;
        src[2] = Bhi + (size_t)(bn + lrow) * K + koff;
        src[3] = Blo + (size_t)(bn + lrow) * K + koff;
        #pragma unroll
        for (int m = 0; m < 4; m++) {
            #pragma unroll
            for (int c = 0; c < 4; c++)
                cpa16(dst0 + m * GMAT + c * 16, (const char*)src[m] + c * 16);
        }
        CPA_COMMIT();
    };

    float acc[2][8][4];
    #pragma unroll
    for (int mt = 0; mt < 2; mt++)
        #pragma unroll
        for (int nt = 0; nt < 8; nt++)
            #pragma unroll
            for (int q = 0; q < 4; q++) acc[mt][nt][q] = 0.f;

    // ldmatrix per-lane address offsets (within a matrix block)
    const uint32_t aOff = (uint32_t)((wm * 32 + (lane & 15)) * GPITCH + (lane >> 4) * 16);
    const uint32_t bOff = (uint32_t)((wn * 64 + (lane & 7) + (lane >> 4) * 8) * GPITCH
                                     + ((lane >> 3) & 1) * 16);

    load_stage(0, 0);

    for (int kt = 0; kt < NK; kt++) {
        const int s = kt & 1;
        if (kt + 1 < NK) {
            load_stage(s ^ 1, kt + 1);
            asm volatile("cp.async.wait_group 1;" ::: "memory");
        } else {
            asm volatile("cp.async.wait_group 0;" ::: "memory");
        }
        __syncthreads();

        const uint32_t base = sb + s * GSTAGE;
        #pragma unroll
        for (int kk = 0; kk < 4; kk++) {
            uint32_t ah[2][4], al[2][4], bh[4][4], bl[4][4];
            #pragma unroll
            for (int mt = 0; mt < 2; mt++) {
                ldsm4(ah[mt], base + 0 * GMAT + aOff + mt * (16 * GPITCH) + kk * 32);
                ldsm4(al[mt], base + 1 * GMAT + aOff + mt * (16 * GPITCH) + kk * 32);
            }
            #pragma unroll
            for (int np = 0; np < 4; np++) {
                ldsm4(bh[np], base + 2 * GMAT + bOff + np * (16 * GPITCH) + kk * 32);
                ldsm4(bl[np], base + 3 * GMAT + bOff + np * (16 * GPITCH) + kk * 32);
            }
            #pragma unroll
            for (int mt = 0; mt < 2; mt++)
                #pragma unroll
                for (int nt = 0; nt < 8; nt++) {
                    const uint32_t* bhp = &bh[nt >> 1][(nt & 1) * 2];
                    const uint32_t* blp = &bl[nt >> 1][(nt & 1) * 2];
                    mma_bf16(acc[mt][nt], ah[mt], bhp);
                    mma_bf16(acc[mt][nt], ah[mt], blp);
                    mma_bf16(acc[mt][nt], al[mt], bhp);
                }
        }
        __syncthreads();
    }

    // ---- epilogue ----
    #pragma unroll
    for (int mt = 0; mt < 2; mt++) {
        const int row0 = bm + wm * 32 + mt * 16 + (lane >> 2);
        #pragma unroll
        for (int nt = 0; nt < 8; nt++) {
            const int col = bn + wn * 64 + nt * 8 + (lane & 3) * 2;
            #pragma unroll
            for (int half = 0; half < 2; half++) {
                const int row = row0 + half * 8;
                const float v0 = acc[mt][nt][half * 2 + 0];
                const float v1 = acc[mt][nt][half * 2 + 1];
                const size_t off = (size_t)row * N + col;
                if (EPI == 0) {
                    float2 v; v.x = v0; v.y = v1;
                    *(float2*)(Cf + off) = v;
                } else if (EPI == 1) {
                    float2 r = *(const float2*)(R + off);
                    float2 v; v.x = r.x + v0; v.y = r.y + v1;
                    *(float2*)(Cf + off) = v;
                } else {
                    float g0 = gelu_exact(v0), g1 = gelu_exact(v1);
                    __nv_bfloat16 h0, h1, l0, l1;
                    split_bf(g0, h0, l0); split_bf(g1, h1, l1);
                    *(__nv_bfloat162*)(Chi + off) = __halves2bfloat162(h0, h1);
                    *(__nv_bfloat162*)(Clo + off) = __halves2bfloat162(l0, l1);
                }
            }
        }
    }
}

// ---------------------------------------------------------------------------
extern "C" void kernel_launch(void* const* d_in, const int* in_sizes, int n_in,
                              void* d_out, int out_size)
{
    const int*   idx     = (const int*)  d_in[0];
    const float* tok_emb = (const float*)d_in[1];
    const float* pos_emb = (const float*)d_in[2];
    const float* ln1_w   = (const float*)d_in[3];
    const float* ln1_b   = (const float*)d_in[4];
    const float* qkv_w   = (const float*)d_in[5];
    const float* out_w   = (const float*)d_in[6];
    const float* ln2_w   = (const float*)d_in[7];
    const float* ln2_b   = (const float*)d_in[8];
    const float* ff1_w   = (const float*)d_in[9];
    const float* ff2_w   = (const float*)d_in[10];
    const float* lnf_w   = (const float*)d_in[11];
    const float* lnf_b   = (const float*)d_in[12];
    float* out = (float*)d_out;

    float *x, *qkv;
    __nv_bfloat16 *h_hi, *h_lo, *y_hi, *y_lo, *ff_hi, *ff_lo;
    __nv_bfloat16 *qkvT_hi, *qkvT_lo, *outT_hi, *outT_lo;
    __nv_bfloat16 *ff1T_hi, *ff1T_lo, *ff2T_hi, *ff2T_lo, *emb_hi, *emb_lo;
    cudaGetSymbolAddress((void**)&x,       g_x);
    cudaGetSymbolAddress((void**)&qkv,     g_qkv);
    cudaGetSymbolAddress((void**)&h_hi,    g_h_hi);
    cudaGetSymbolAddress((void**)&h_lo,    g_h_lo);
    cudaGetSymbolAddress((void**)&y_hi,    g_y_hi);
    cudaGetSymbolAddress((void**)&y_lo,    g_y_lo);
    cudaGetSymbolAddress((void**)&ff_hi,   g_ff_hi);
    cudaGetSymbolAddress((void**)&ff_lo,   g_ff_lo);
    cudaGetSymbolAddress((void**)&qkvT_hi, g_qkvT_hi);
    cudaGetSymbolAddress((void**)&qkvT_lo, g_qkvT_lo);
    cudaGetSymbolAddress((void**)&outT_hi, g_outT_hi);
    cudaGetSymbolAddress((void**)&outT_lo, g_outT_lo);
    cudaGetSymbolAddress((void**)&ff1T_hi, g_ff1T_hi);
    cudaGetSymbolAddress((void**)&ff1T_lo, g_ff1T_lo);
    cudaGetSymbolAddress((void**)&ff2T_hi, g_ff2T_hi);
    cudaGetSymbolAddress((void**)&ff2T_lo, g_ff2T_lo);
    cudaGetSymbolAddress((void**)&emb_hi,  g_emb_hi);
    cudaGetSymbolAddress((void**)&emb_lo,  g_emb_lo);

    const int FLASH_SMEM = (4 * 64 * FPAD + 3 * 64) * sizeof(float);
    cudaFuncSetAttribute(flash_kernel,
                         cudaFuncAttributeMaxDynamicSharedMemorySize, FLASH_SMEM);
    cudaFuncSetAttribute(gemm_mma<0>,
                         cudaFuncAttributeMaxDynamicSharedMemorySize, GEMM_SMEM);
    cudaFuncSetAttribute(gemm_mma<1>,
                         cudaFuncAttributeMaxDynamicSharedMemorySize, GEMM_SMEM);
    cudaFuncSetAttribute(gemm_mma<2>,
                         cudaFuncAttributeMaxDynamicSharedMemorySize, GEMM_SMEM);

    // ---- weight prep ----
    wprep_S<<<8192, 256>>>((const float4*)tok_emb, emb_hi, emb_lo, VV * DD / 4);
    for (int l = 0; l < LL; l++) {
        wprep_T<<<dim3(3*DD/32, DD/32), 256>>>(
            qkv_w + (size_t)l*DD*3*DD, qkvT_hi + (size_t)l*3*DD*DD,
            qkvT_lo + (size_t)l*3*DD*DD, DD, 3*DD);
        wprep_T<<<dim3(DD/32, DD/32), 256>>>(
            out_w + (size_t)l*DD*DD, outT_hi + (size_t)l*DD*DD,
            outT_lo + (size_t)l*DD*DD, DD, DD);
        wprep_T<<<dim3(4*DD/32, DD/32), 256>>>(
            ff1_w + (size_t)l*DD*4*DD, ff1T_hi + (size_t)l*4*DD*DD,
            ff1T_lo + (size_t)l*4*DD*DD, DD, 4*DD);
        wprep_T<<<dim3(DD/32, 4*DD/32), 256>>>(
            ff2_w + (size_t)l*4*DD*DD, ff2T_hi + (size_t)l*4*DD*DD,
            ff2T_lo + (size_t)l*4*DD*DD, 4*DD, DD);
    }

    embed_kernel<<<MM, 256>>>(idx, tok_emb, pos_emb, x);

    for (int l = 0; l < LL; l++) {
        ln_kernel<<<MM, 256>>>(x, ln1_w + l*DD, ln1_b + l*DD, h_hi, h_lo);
        gemm_mma<0><<<dim3(3*DD/128, MM/128), 256, GEMM_SMEM>>>(
            h_hi, h_lo, qkvT_hi + (size_t)l*3*DD*DD, qkvT_lo + (size_t)l*3*DD*DD,
            nullptr, qkv, nullptr, nullptr, MM, 3*DD, DD);
        flash_kernel<<<dim3(TT/64, HH, BB), 256, FLASH_SMEM>>>(qkv, y_hi, y_lo);
        gemm_mma<1><<<dim3(DD/128, MM/128), 256, GEMM_SMEM>>>(
            y_hi, y_lo, outT_hi + (size_t)l*DD*DD, outT_lo + (size_t)l*DD*DD,
            x, x, nullptr, nullptr, MM, DD, DD);
        ln_kernel<<<MM, 256>>>(x, ln2_w + l*DD, ln2_b + l*DD, h_hi, h_lo);
        gemm_mma<2><<<dim3(4*DD/128, MM/128), 256, GEMM_SMEM>>>(
            h_hi, h_lo, ff1T_hi + (size_t)l*4*DD*DD, ff1T_lo + (size_t)l*4*DD*DD,
            nullptr, nullptr, ff_hi, ff_lo, MM, 4*DD, DD);
        gemm_mma<1><<<dim3(DD/128, MM/128), 256, GEMM_SMEM>>>(
            ff_hi, ff_lo, ff2T_hi + (size_t)l*4*DD*DD, ff2T_lo + (size_t)l*4*DD*DD,
            x, x, nullptr, nullptr, MM, DD, 4*DD);
    }

    ln_kernel<<<MM, 256>>>(x, lnf_w, lnf_b, h_hi, h_lo);
    gemm_mma<0><<<dim3(VV/128, MM/128), 256, GEMM_SMEM>>>(
        h_hi, h_lo, emb_hi, emb_lo, nullptr, out, nullptr, nullptr, MM, VV, DD);
}